// round 1
// baseline (speedup 1.0000x reference)
#include <cuda_runtime.h>

#define BN   8
#define HH   720
#define WW   1280
#define NPIX (HH * WW)
#define TOT  (BN * NPIX)
#define BIGF 1e30f

// Scratch (allocation-free rule: __device__ globals)
__device__ unsigned int g_mind[TOT];
__device__ float        g_cnt [TOT];

__global__ __launch_bounds__(256)
void k_init(float* __restrict__ out) {
    int i = blockIdx.x * blockDim.x + threadIdx.x;
    if (i >= TOT) return;
    g_mind[i] = __float_as_uint(BIGF);
    g_cnt[i]  = 0.0f;
    int b = i / NPIX;
    int p = i - b * NPIX;
    out[(size_t)(b * 2 + 0) * NPIX + p] = 0.0f;
    out[(size_t)(b * 2 + 1) * NPIX + p] = 0.0f;
}

__device__ __forceinline__ bool compute_targets(
    const float* __restrict__ flow, int i,
    int& b, int& p, float& fx, float& fy,
    int& t0, int& t1, int& t2, int& t3)
{
    b = i / NPIX;
    p = i - b * NPIX;
    int y = p / WW;
    int x = p - y * WW;
    fx = flow[(size_t)(b * 2 + 0) * NPIX + p];
    fy = flow[(size_t)(b * 2 + 1) * NPIX + p];
    float x2 = (float)x + fx;
    float y2 = (float)y + fy;
    if (!(x2 >= 0.0f && y2 >= 0.0f && x2 <= (float)(WW - 1) && y2 <= (float)(HH - 1)))
        return false;
    int xL = (int)floorf(x2); xL = max(0, min(xL, WW - 1));
    int yT = (int)floorf(y2); yT = max(0, min(yT, HH - 1));
    int xR = min(xL + 1, WW - 1);
    int yB = min(yT + 1, HH - 1);
    t0 = yT * WW + xL;
    t1 = yT * WW + xR;
    t2 = yB * WW + xL;
    t3 = yB * WW + xR;
    return true;
}

__global__ __launch_bounds__(256)
void k_min(const float* __restrict__ flow, const float* __restrict__ depth) {
    int i = blockIdx.x * blockDim.x + threadIdx.x;
    if (i >= TOT) return;
    int b, p, t0, t1, t2, t3;
    float fx, fy;
    if (!compute_targets(flow, i, b, p, fx, fy, t0, t1, t2, t3)) return;
    unsigned int du = __float_as_uint(depth[(size_t)b * NPIX + p]);
    unsigned int* base = g_mind + (size_t)b * NPIX;
    atomicMin(&base[t0], du);
    atomicMin(&base[t1], du);
    atomicMin(&base[t2], du);
    atomicMin(&base[t3], du);
}

__global__ __launch_bounds__(256)
void k_select(const float* __restrict__ flow, const float* __restrict__ depth,
              float* __restrict__ out) {
    int i = blockIdx.x * blockDim.x + threadIdx.x;
    if (i >= TOT) return;
    int b, p, t0, t1, t2, t3;
    float fx, fy;
    if (!compute_targets(flow, i, b, p, fx, fy, t0, t1, t2, t3)) return;
    unsigned int du = __float_as_uint(depth[(size_t)b * NPIX + p]);
    const unsigned int* mbase = g_mind + (size_t)b * NPIX;
    float* outx = out + (size_t)(b * 2 + 0) * NPIX;
    float* outy = out + (size_t)(b * 2 + 1) * NPIX;
    float* cbase = g_cnt + (size_t)b * NPIX;

    int ts[4] = {t0, t1, t2, t3};
#pragma unroll
    for (int k = 0; k < 4; k++) {
        int t = ts[k];
        if (mbase[t] == du) {
            atomicAdd(&outx[t], -fx);
            atomicAdd(&outy[t], -fy);
            atomicAdd(&cbase[t], 1.0f);
        }
    }
}

__global__ __launch_bounds__(256)
void k_norm(float* __restrict__ out) {
    int i = blockIdx.x * blockDim.x + threadIdx.x;
    if (i >= TOT) return;
    float c = g_cnt[i];
    int b = i / NPIX;
    int p = i - b * NPIX;
    size_t ix = (size_t)(b * 2 + 0) * NPIX + p;
    size_t iy = (size_t)(b * 2 + 1) * NPIX + p;
    if (c > 0.0f) {
        float inv = 1.0f / c;
        out[ix] *= inv;
        out[iy] *= inv;
    } else {
        out[ix] = 0.0f;
        out[iy] = 0.0f;
    }
}

extern "C" void kernel_launch(void* const* d_in, const int* in_sizes, int n_in,
                              void* d_out, int out_size) {
    const float* flow  = (const float*)d_in[0];   // (B,2,H,W)
    const float* depth = (const float*)d_in[1];   // (B,1,H,W)
    float* out = (float*)d_out;                   // (B,2,H,W)

    const int threads = 256;
    const int blocks  = (TOT + threads - 1) / threads;

    k_init  <<<blocks, threads>>>(out);
    k_min   <<<blocks, threads>>>(flow, depth);
    k_select<<<blocks, threads>>>(flow, depth, out);
    k_norm  <<<blocks, threads>>>(out);
}